// round 1
// baseline (speedup 1.0000x reference)
#include <cuda_runtime.h>
#include <cuda_bf16.h>
#include <math.h>

// ---------------- problem constants ----------------
#define LAYERS 12
#define DMODEL 768
#define NHEAD  12
#define HD     64
#define TMAXS  1024
#define BATCH  2
#define MROWS  (BATCH*TMAXS)   // 2048
#define VOCAB  50257

// ---------------- scratch (no allocation allowed) ----------------
__device__ float g_x  [MROWS*DMODEL];
__device__ float g_h  [MROWS*DMODEL];
__device__ float g_qkv[MROWS*3*DMODEL];
__device__ float g_y  [MROWS*DMODEL];
__device__ float g_fc [MROWS*4*DMODEL];

// ---------------- helpers ----------------
__device__ __forceinline__ float warp_max(float v){
    #pragma unroll
    for(int o=16;o;o>>=1) v = fmaxf(v, __shfl_xor_sync(0xffffffffu, v, o));
    return v;
}
__device__ __forceinline__ float warp_sum(float v){
    #pragma unroll
    for(int o=16;o;o>>=1) v += __shfl_xor_sync(0xffffffffu, v, o);
    return v;
}
__device__ __forceinline__ float gelu_exact(float v){
    return 0.5f * v * (1.0f + erff(v * 0.70710678118654752440f));
}

// ---------------- embedding: x = wte[ids] + wpe[t] ----------------
__global__ void embed_kernel(const int* __restrict__ ids,
                             const float* __restrict__ wte,
                             const float* __restrict__ wpe,
                             float* __restrict__ x)
{
    int i = blockIdx.x * blockDim.x + threadIdx.x;   // over MROWS*DMODEL
    if (i >= MROWS*DMODEL) return;
    int row = i / DMODEL;
    int d   = i - row*DMODEL;
    int t   = row & (TMAXS-1);
    int id  = ids[row];
    x[i] = wte[(size_t)id*DMODEL + d] + wpe[(size_t)t*DMODEL + d];
}

// ---------------- layernorm: one block per row ----------------
__global__ void layernorm_kernel(const float* __restrict__ in,
                                 float* __restrict__ out,
                                 const float* __restrict__ g,
                                 const float* __restrict__ b)
{
    int row = blockIdx.x;
    const float* x = in + (size_t)row*DMODEL;
    float s = 0.f, ss = 0.f;
    for (int i = threadIdx.x; i < DMODEL; i += 256){
        float v = x[i]; s += v; ss += v*v;
    }
    __shared__ float sbuf[8], sbuf2[8];
    s  = warp_sum(s);
    ss = warp_sum(ss);
    if ((threadIdx.x & 31) == 0){ sbuf[threadIdx.x>>5] = s; sbuf2[threadIdx.x>>5] = ss; }
    __syncthreads();
    if (threadIdx.x == 0){
        float S=0.f, SS=0.f;
        #pragma unroll
        for (int i=0;i<8;i++){ S += sbuf[i]; SS += sbuf2[i]; }
        sbuf[0]  = S * (1.0f/DMODEL);
        sbuf2[0] = SS * (1.0f/DMODEL);
    }
    __syncthreads();
    float mean = sbuf[0];
    float var  = sbuf2[0] - mean*mean;
    float rstd = rsqrtf(var + 1e-5f);
    float* o = out + (size_t)row*DMODEL;
    for (int i = threadIdx.x; i < DMODEL; i += 256)
        o[i] = (x[i]-mean)*rstd*g[i] + b[i];
}

// ---------------- SGEMM NN: C[M,N] = A[M,K] @ B[K,N] (+ epilogue) -----------
// epi: 0 none, 1 +bias, 2 +bias+resid, 3 +bias+gelu
// M,N multiples of 128; K multiple of 16 (true for all NN calls here).
__global__ __launch_bounds__(256) void sgemm_nn(
    const float* __restrict__ A, const float* __restrict__ B,
    const float* __restrict__ bias, const float* __restrict__ resid,
    float* __restrict__ C, int M, int N, int K, int epi)
{
    __shared__ float As[16][128];
    __shared__ float Bs[16][128];
    const int tid = threadIdx.x;
    const int bm = blockIdx.y * 128;
    const int bn = blockIdx.x * 128;
    const int tx = tid & 15, ty = tid >> 4;

    float acc[8][8];
    #pragma unroll
    for (int i=0;i<8;i++)
        #pragma unroll
        for (int j=0;j<8;j++) acc[i][j]=0.f;

    for (int k0 = 0; k0 < K; k0 += 16){
        #pragma unroll
        for (int r=0;r<2;r++){
            int j   = tid + r*256;
            int row = j >> 2;
            int kq  = (j & 3) << 2;
            float4 v = *(const float4*)(A + (size_t)(bm+row)*K + k0 + kq);
            As[kq+0][row]=v.x; As[kq+1][row]=v.y; As[kq+2][row]=v.z; As[kq+3][row]=v.w;
        }
        #pragma unroll
        for (int r=0;r<2;r++){
            int j  = tid + r*256;
            int kr = j >> 5;
            int cq = (j & 31) << 2;
            *(float4*)(&Bs[kr][cq]) = *(const float4*)(B + (size_t)(k0+kr)*N + bn + cq);
        }
        __syncthreads();
        #pragma unroll
        for (int kk=0;kk<16;kk++){
            float a[8], bb[8];
            *(float4*)(a)   = *(const float4*)(&As[kk][ty*8]);
            *(float4*)(a+4) = *(const float4*)(&As[kk][ty*8+4]);
            *(float4*)(bb)   = *(const float4*)(&Bs[kk][tx*8]);
            *(float4*)(bb+4) = *(const float4*)(&Bs[kk][tx*8+4]);
            #pragma unroll
            for (int i=0;i<8;i++)
                #pragma unroll
                for (int j=0;j<8;j++)
                    acc[i][j] += a[i]*bb[j];
        }
        __syncthreads();
    }

    #pragma unroll
    for (int i=0;i<8;i++){
        int row = bm + ty*8 + i;
        float* crow = C + (size_t)row*N + bn + tx*8;
        const float* rrow = resid + (size_t)row*N + bn + tx*8;
        #pragma unroll
        for (int j=0;j<8;j++){
            float v = acc[i][j];
            if (epi >= 1) v += bias[bn + tx*8 + j];
            if (epi == 2) v += rrow[j];
            if (epi == 3) v = gelu_exact(v);
            crow[j] = v;
        }
    }
}

// ---------------- SGEMM NT: C[M,N] = A[M,K] @ Bt[N,K]^T  (lm head) ---------
__global__ __launch_bounds__(256) void sgemm_nt(
    const float* __restrict__ A, const float* __restrict__ Bt,
    float* __restrict__ C, int M, int N, int K)
{
    __shared__ float As[16][128];
    __shared__ float Bs[16][128];
    const int tid = threadIdx.x;
    const int bm = blockIdx.y * 128;
    const int bn = blockIdx.x * 128;
    const int tx = tid & 15, ty = tid >> 4;

    float acc[8][8];
    #pragma unroll
    for (int i=0;i<8;i++)
        #pragma unroll
        for (int j=0;j<8;j++) acc[i][j]=0.f;

    for (int k0 = 0; k0 < K; k0 += 16){
        #pragma unroll
        for (int r=0;r<2;r++){
            int j   = tid + r*256;
            int row = j >> 2;
            int kq  = (j & 3) << 2;
            float4 v = *(const float4*)(A + (size_t)(bm+row)*K + k0 + kq);
            As[kq+0][row]=v.x; As[kq+1][row]=v.y; As[kq+2][row]=v.z; As[kq+3][row]=v.w;
        }
        #pragma unroll
        for (int r=0;r<2;r++){
            int j   = tid + r*256;
            int row = j >> 2;
            int kq  = (j & 3) << 2;
            int n   = bn + row;
            float4 v = make_float4(0.f,0.f,0.f,0.f);
            if (n < N) v = *(const float4*)(Bt + (size_t)n*K + k0 + kq);
            Bs[kq+0][row]=v.x; Bs[kq+1][row]=v.y; Bs[kq+2][row]=v.z; Bs[kq+3][row]=v.w;
        }
        __syncthreads();
        #pragma unroll
        for (int kk=0;kk<16;kk++){
            float a[8], bb[8];
            *(float4*)(a)   = *(const float4*)(&As[kk][ty*8]);
            *(float4*)(a+4) = *(const float4*)(&As[kk][ty*8+4]);
            *(float4*)(bb)   = *(const float4*)(&Bs[kk][tx*8]);
            *(float4*)(bb+4) = *(const float4*)(&Bs[kk][tx*8+4]);
            #pragma unroll
            for (int i=0;i<8;i++)
                #pragma unroll
                for (int j=0;j<8;j++)
                    acc[i][j] += a[i]*bb[j];
        }
        __syncthreads();
    }

    #pragma unroll
    for (int i=0;i<8;i++){
        int row = bm + ty*8 + i;
        float* crow = C + (size_t)row*N;
        #pragma unroll
        for (int j=0;j<8;j++){
            int col = bn + tx*8 + j;
            if (col < N) crow[col] = acc[i][j];
        }
    }
}

// ---------------- attention: one block per (query row, head, batch) --------
// qkv layout per row: [q(768) | k(768) | v(768)], head h at offset h*64.
__global__ __launch_bounds__(128) void attention_kernel(
    const float* __restrict__ qkv, float* __restrict__ y)
{
    const int tq = blockIdx.x;
    const int h  = blockIdx.y;
    const int b  = blockIdx.z;
    const int tid = threadIdx.x;

    __shared__ float sq[HD];
    __shared__ float sp[TMAXS];
    __shared__ float rmax[4], rsum[4];
    __shared__ float yc[HD];

    const size_t rowbase = (size_t)(b*TMAXS + tq) * (3*DMODEL);
    if (tid < HD) sq[tid] = qkv[rowbase + h*HD + tid];
    __syncthreads();

    const int nk = tq + 1;

    // scores
    float lmax = -INFINITY;
    for (int k = tid; k < nk; k += 128){
        const float* kr = qkv + (size_t)(b*TMAXS + k)*(3*DMODEL) + DMODEL + h*HD;
        float dot = 0.f;
        #pragma unroll
        for (int d = 0; d < HD; d += 4){
            float4 kv = *(const float4*)(kr + d);
            dot += sq[d]*kv.x + sq[d+1]*kv.y + sq[d+2]*kv.z + sq[d+3]*kv.w;
        }
        dot *= 0.125f;           // 1/sqrt(64)
        sp[k] = dot;
        lmax = fmaxf(lmax, dot);
    }
    float wm = warp_max(lmax);
    if ((tid & 31) == 0) rmax[tid>>5] = wm;
    __syncthreads();
    float gmax = fmaxf(fmaxf(rmax[0],rmax[1]), fmaxf(rmax[2],rmax[3]));

    // exp + sum
    float lsum = 0.f;
    for (int k = tid; k < nk; k += 128){
        float e = __expf(sp[k] - gmax);
        sp[k] = e;
        lsum += e;
    }
    float ws = warp_sum(lsum);
    if ((tid & 31) == 0) rsum[tid>>5] = ws;
    __syncthreads();             // also makes sp[] globally visible
    float inv = 1.0f / (rsum[0]+rsum[1]+rsum[2]+rsum[3]);

    // y[d] = sum_k p[k] * V[k][d]
    const int d    = tid & 63;
    const int half = tid >> 6;
    float acc = 0.f;
    for (int k = half; k < nk; k += 2){
        acc += sp[k] * qkv[(size_t)(b*TMAXS + k)*(3*DMODEL) + 2*DMODEL + h*HD + d];
    }
    if (half) yc[d] = acc;
    __syncthreads();
    if (!half)
        y[(size_t)(b*TMAXS + tq)*DMODEL + h*HD + d] = (acc + yc[d]) * inv;
}

// ---------------- host orchestration ----------------
extern "C" void kernel_launch(void* const* d_in, const int* in_sizes, int n_in,
                              void* d_out, int out_size)
{
    const int*   ids    = (const int*)  d_in[0];
    const float* wte    = (const float*)d_in[1];
    const float* wpe    = (const float*)d_in[2];
    const float* ln1_g  = (const float*)d_in[3];
    const float* ln1_b  = (const float*)d_in[4];
    const float* attn_w = (const float*)d_in[5];
    const float* attn_b = (const float*)d_in[6];
    const float* proj_w = (const float*)d_in[7];
    const float* proj_b = (const float*)d_in[8];
    const float* ln2_g  = (const float*)d_in[9];
    const float* ln2_b  = (const float*)d_in[10];
    const float* fc_w   = (const float*)d_in[11];
    const float* fc_b   = (const float*)d_in[12];
    const float* fc2_w  = (const float*)d_in[13];
    const float* fc2_b  = (const float*)d_in[14];
    const float* lnf_g  = (const float*)d_in[15];
    const float* lnf_b  = (const float*)d_in[16];
    float* out = (float*)d_out;

    float *x, *h, *qkv, *y, *fc;
    cudaGetSymbolAddress((void**)&x,   g_x);
    cudaGetSymbolAddress((void**)&h,   g_h);
    cudaGetSymbolAddress((void**)&qkv, g_qkv);
    cudaGetSymbolAddress((void**)&y,   g_y);
    cudaGetSymbolAddress((void**)&fc,  g_fc);

    embed_kernel<<<(MROWS*DMODEL + 255)/256, 256>>>(ids, wte, wpe, x);

    for (int l = 0; l < LAYERS; l++){
        layernorm_kernel<<<MROWS, 256>>>(x, h, ln1_g + l*DMODEL, ln1_b + l*DMODEL);

        sgemm_nn<<<dim3(3*DMODEL/128, MROWS/128), 256>>>(
            h, attn_w + (size_t)l*DMODEL*3*DMODEL, attn_b + (size_t)l*3*DMODEL,
            nullptr, qkv, MROWS, 3*DMODEL, DMODEL, 1);

        attention_kernel<<<dim3(TMAXS, NHEAD, BATCH), 128>>>(qkv, y);

        sgemm_nn<<<dim3(DMODEL/128, MROWS/128), 256>>>(
            y, proj_w + (size_t)l*DMODEL*DMODEL, proj_b + (size_t)l*DMODEL,
            x, x, MROWS, DMODEL, DMODEL, 2);

        layernorm_kernel<<<MROWS, 256>>>(x, h, ln2_g + l*DMODEL, ln2_b + l*DMODEL);

        sgemm_nn<<<dim3(4*DMODEL/128, MROWS/128), 256>>>(
            h, fc_w + (size_t)l*DMODEL*4*DMODEL, fc_b + (size_t)l*4*DMODEL,
            nullptr, fc, MROWS, 4*DMODEL, DMODEL, 3);

        sgemm_nn<<<dim3(DMODEL/128, MROWS/128), 256>>>(
            fc, fc2_w + (size_t)l*4*DMODEL*DMODEL, fc2_b + (size_t)l*DMODEL,
            x, x, MROWS, DMODEL, 4*DMODEL, 2);
    }

    layernorm_kernel<<<MROWS, 256>>>(x, h, lnf_g, lnf_b);

    sgemm_nt<<<dim3((VOCAB + 127)/128, MROWS/128), 256>>>(
        h, wte, out, MROWS, VOCAB, DMODEL);
}

// round 2
// speedup vs baseline: 1.6439x; 1.6439x over previous
#include <cuda_runtime.h>
#include <cuda_bf16.h>
#include <math.h>

// ---------------- problem constants ----------------
#define LAYERS 12
#define DMODEL 768
#define NHEAD  12
#define HD     64
#define TMAXS  1024
#define BATCH  2
#define MROWS  (BATCH*TMAXS)   // 2048
#define VOCAB  50257

// ---------------- scratch (no allocation allowed) ----------------
__device__ float g_x  [MROWS*DMODEL];
__device__ float g_h  [MROWS*DMODEL];
__device__ float g_qkv[MROWS*3*DMODEL];
__device__ float g_y  [MROWS*DMODEL];
__device__ float g_fc [MROWS*4*DMODEL];

// ---------------- helpers ----------------
__device__ __forceinline__ float warp_max(float v){
    #pragma unroll
    for(int o=16;o;o>>=1) v = fmaxf(v, __shfl_xor_sync(0xffffffffu, v, o));
    return v;
}
__device__ __forceinline__ float warp_sum(float v){
    #pragma unroll
    for(int o=16;o;o>>=1) v += __shfl_xor_sync(0xffffffffu, v, o);
    return v;
}
__device__ __forceinline__ float gelu_exact(float v){
    return 0.5f * v * (1.0f + erff(v * 0.70710678118654752440f));
}
__device__ __forceinline__ unsigned f2tf32(float v){
    unsigned u;
    asm("cvt.rna.tf32.f32 %0, %1;" : "=r"(u) : "f"(v));
    return u;
}
__device__ __forceinline__ void cp16(unsigned dst, const void* src, bool pred){
    int bytes = pred ? 16 : 0;
    asm volatile("cp.async.cg.shared.global [%0], [%1], 16, %2;\n"
                 :: "r"(dst), "l"(src), "r"(bytes));
}
#define CP_COMMIT() asm volatile("cp.async.commit_group;\n" ::: "memory")
#define CP_WAIT1()  asm volatile("cp.async.wait_group 1;\n" ::: "memory")

__device__ __forceinline__ void mma_tf32(float c[4], const unsigned a[4], const unsigned b[2]){
    asm volatile(
        "mma.sync.aligned.m16n8k8.row.col.f32.tf32.tf32.f32 "
        "{%0,%1,%2,%3}, {%4,%5,%6,%7}, {%8,%9}, {%0,%1,%2,%3};\n"
        : "+f"(c[0]), "+f"(c[1]), "+f"(c[2]), "+f"(c[3])
        : "r"(a[0]), "r"(a[1]), "r"(a[2]), "r"(a[3]), "r"(b[0]), "r"(b[1]));
}

// ---------------- embedding ----------------
__global__ void embed_kernel(const int* __restrict__ ids,
                             const float* __restrict__ wte,
                             const float* __restrict__ wpe,
                             float* __restrict__ x)
{
    int i = blockIdx.x * blockDim.x + threadIdx.x;
    if (i >= MROWS*DMODEL) return;
    int row = i / DMODEL;
    int d   = i - row*DMODEL;
    int t   = row & (TMAXS-1);
    int id  = ids[row];
    x[i] = wte[(size_t)id*DMODEL + d] + wpe[(size_t)t*DMODEL + d];
}

// ---------------- layernorm ----------------
__global__ void layernorm_kernel(const float* __restrict__ in,
                                 float* __restrict__ out,
                                 const float* __restrict__ g,
                                 const float* __restrict__ b)
{
    int row = blockIdx.x;
    const float* x = in + (size_t)row*DMODEL;
    float s = 0.f, ss = 0.f;
    for (int i = threadIdx.x; i < DMODEL; i += 256){
        float v = x[i]; s += v; ss += v*v;
    }
    __shared__ float sbuf[8], sbuf2[8];
    s  = warp_sum(s);
    ss = warp_sum(ss);
    if ((threadIdx.x & 31) == 0){ sbuf[threadIdx.x>>5] = s; sbuf2[threadIdx.x>>5] = ss; }
    __syncthreads();
    if (threadIdx.x == 0){
        float S=0.f, SS=0.f;
        #pragma unroll
        for (int i=0;i<8;i++){ S += sbuf[i]; SS += sbuf2[i]; }
        sbuf[0]  = S * (1.0f/DMODEL);
        sbuf2[0] = SS * (1.0f/DMODEL);
    }
    __syncthreads();
    float mean = sbuf[0];
    float var  = sbuf2[0] - mean*mean;
    float rstd = rsqrtf(var + 1e-5f);
    float* o = out + (size_t)row*DMODEL;
    for (int i = threadIdx.x; i < DMODEL; i += 256)
        o[i] = (x[i]-mean)*rstd*g[i] + b[i];
}

// =====================================================================
// TF32 tensor-core GEMM.
//   BT=false: C[M,N] = A[M,K] @ B[K,N]   (B row-major, M,N mult of 128)
//   BT=true : C[M,N] = A[M,K] @ Bt[N,K]^T (lm head; N ragged)
// EPI: 0 none, 1 +bias, 2 +bias+resid, 3 +bias+gelu
// Block 128x128x32, 256 thr, 8 warps (2x4), warp tile 64x32.
// SMEM (double buffered, dynamic):
//   As: [2][128][36]  (bank-conflict-free for m16k8 A frag reads)
//   Bs NN: [2][32][136]  (k-major, stride 136 -> conflict-free frag reads)
//   Bs NT: [2][128][36]  (n-major)
// =====================================================================
#define AS_STRIDE 36
#define BS_NN_STRIDE 136
#define AS_BUF (128*AS_STRIDE)
#define BS_NN_BUF (32*BS_NN_STRIDE)
#define BS_NT_BUF (128*AS_STRIDE)

template<int EPI, bool BT>
__global__ __launch_bounds__(256) void mma_gemm(
    const float* __restrict__ A, const float* __restrict__ B,
    const float* __restrict__ bias, const float* __restrict__ resid,
    float* __restrict__ C, int M, int N, int K)
{
    extern __shared__ float smem[];
    float* As = smem;
    float* Bs = smem + 2*AS_BUF;

    const int tid  = threadIdx.x;
    const int lane = tid & 31;
    const int warp = tid >> 5;
    const int wm   = warp >> 2;        // 0..1
    const int wn   = warp & 3;         // 0..3
    const int bm   = blockIdx.y * 128;
    const int bn   = blockIdx.x * 128;

    unsigned s_as = (unsigned)__cvta_generic_to_shared(As);
    unsigned s_bs = (unsigned)__cvta_generic_to_shared(Bs);

    const int T = K / 32;

    // tile loader
    auto load_tile = [&](int t, int buf){
        int k0 = t * 32;
        // A: 128x32, thread loads 4 float4
        #pragma unroll
        for (int p = 0; p < 4; p++){
            int row = (tid >> 3) + p*32;
            int c4  = (tid & 7) * 4;
            const float* src = A + (size_t)(bm+row)*K + k0 + c4;
            unsigned dst = s_as + (buf*AS_BUF + row*AS_STRIDE + c4)*4u;
            cp16(dst, src, true);
        }
        if (!BT){
            // B: 32x128 row-major -> Bs[k][n] stride 136
            #pragma unroll
            for (int p = 0; p < 4; p++){
                int j  = tid + p*256;
                int kr = j >> 5;
                int cq = (j & 31) * 4;
                const float* src = B + (size_t)(k0+kr)*N + bn + cq;
                unsigned dst = s_bs + (buf*BS_NN_BUF + kr*BS_NN_STRIDE + cq)*4u;
                cp16(dst, src, true);
            }
        } else {
            // Bt: rows n (ragged), cols k -> Bs[n][k] stride 36
            #pragma unroll
            for (int p = 0; p < 4; p++){
                int j  = tid + p*256;
                int n  = j >> 3;
                int kq = (j & 7) * 4;
                bool ok = (bn + n) < N;
                const float* src = ok ? (B + (size_t)(bn+n)*K + k0 + kq) : B;
                unsigned dst = s_bs + (buf*BS_NT_BUF + n*AS_STRIDE + kq)*4u;
                cp16(dst, src, ok);
            }
        }
    };

    float acc[4][4][4];
    #pragma unroll
    for (int i=0;i<4;i++)
        #pragma unroll
        for (int j=0;j<4;j++)
            #pragma unroll
            for (int r=0;r<4;r++) acc[i][j][r]=0.f;

    load_tile(0, 0);
    CP_COMMIT();

    for (int t = 0; t < T; t++){
        if (t + 1 < T) load_tile(t+1, (t+1)&1);
        CP_COMMIT();
        CP_WAIT1();
        __syncthreads();

        const float* Ab = As + (t&1)*AS_BUF;
        const float* Bb = Bs + (t&1)*(BT ? BS_NT_BUF : BS_NN_BUF);

        #pragma unroll
        for (int ks = 0; ks < 4; ks++){
            int kk = ks*8;
            unsigned af[4][4];
            #pragma unroll
            for (int mt = 0; mt < 4; mt++){
                int r0 = wm*64 + mt*16 + (lane>>2);
                int c0 = kk + (lane&3);
                af[mt][0] = f2tf32(Ab[ r0     *AS_STRIDE + c0    ]);
                af[mt][1] = f2tf32(Ab[(r0+8)  *AS_STRIDE + c0    ]);
                af[mt][2] = f2tf32(Ab[ r0     *AS_STRIDE + c0 + 4]);
                af[mt][3] = f2tf32(Ab[(r0+8)  *AS_STRIDE + c0 + 4]);
            }
            unsigned bf[4][2];
            #pragma unroll
            for (int nt = 0; nt < 4; nt++){
                int n = wn*32 + nt*8 + (lane>>2);
                int k = kk + (lane&3);
                if (!BT){
                    bf[nt][0] = f2tf32(Bb[ k     *BS_NN_STRIDE + n]);
                    bf[nt][1] = f2tf32(Bb[(k+4)  *BS_NN_STRIDE + n]);
                } else {
                    bf[nt][0] = f2tf32(Bb[n*AS_STRIDE + k    ]);
                    bf[nt][1] = f2tf32(Bb[n*AS_STRIDE + k + 4]);
                }
            }
            #pragma unroll
            for (int mt = 0; mt < 4; mt++)
                #pragma unroll
                for (int nt = 0; nt < 4; nt++)
                    mma_tf32(acc[mt][nt], af[mt], bf[nt]);
        }
        __syncthreads();
    }

    // epilogue
    #pragma unroll
    for (int mt = 0; mt < 4; mt++){
        #pragma unroll
        for (int nt = 0; nt < 4; nt++){
            int col  = bn + wn*32 + nt*8 + 2*(lane&3);
            int row0 = bm + wm*64 + mt*16 + (lane>>2);
            float b0 = 0.f, b1 = 0.f;
            if (EPI >= 1){
                if (!BT || col   < N) b0 = bias[col];
                if (!BT || col+1 < N) b1 = bias[col+1];
            }
            #pragma unroll
            for (int half = 0; half < 2; half++){
                int row = row0 + half*8;
                float v0 = acc[mt][nt][half*2+0] + b0;
                float v1 = acc[mt][nt][half*2+1] + b1;
                if (EPI == 2){
                    v0 += resid[(size_t)row*N + col];
                    v1 += resid[(size_t)row*N + col + 1];
                }
                if (EPI == 3){ v0 = gelu_exact(v0); v1 = gelu_exact(v1); }
                if (!BT){
                    *(float2*)(C + (size_t)row*N + col) = make_float2(v0, v1);
                } else {
                    if (col   < N) C[(size_t)row*N + col]     = v0;
                    if (col+1 < N) C[(size_t)row*N + col + 1] = v1;
                }
            }
        }
    }
}

// ---------------- attention ----------------
__global__ __launch_bounds__(128) void attention_kernel(
    const float* __restrict__ qkv, float* __restrict__ y)
{
    const int tq = blockIdx.x;
    const int h  = blockIdx.y;
    const int b  = blockIdx.z;
    const int tid = threadIdx.x;

    __shared__ float sq[HD];
    __shared__ float sp[TMAXS];
    __shared__ float rmax[4], rsum[4];
    __shared__ float yc[HD];

    const size_t rowbase = (size_t)(b*TMAXS + tq) * (3*DMODEL);
    if (tid < HD) sq[tid] = qkv[rowbase + h*HD + tid];
    __syncthreads();

    const int nk = tq + 1;

    float lmax = -INFINITY;
    for (int k = tid; k < nk; k += 128){
        const float* kr = qkv + (size_t)(b*TMAXS + k)*(3*DMODEL) + DMODEL + h*HD;
        float dot = 0.f;
        #pragma unroll
        for (int d = 0; d < HD; d += 4){
            float4 kv = *(const float4*)(kr + d);
            dot += sq[d]*kv.x + sq[d+1]*kv.y + sq[d+2]*kv.z + sq[d+3]*kv.w;
        }
        dot *= 0.125f;
        sp[k] = dot;
        lmax = fmaxf(lmax, dot);
    }
    float wm = warp_max(lmax);
    if ((tid & 31) == 0) rmax[tid>>5] = wm;
    __syncthreads();
    float gmax = fmaxf(fmaxf(rmax[0],rmax[1]), fmaxf(rmax[2],rmax[3]));

    float lsum = 0.f;
    for (int k = tid; k < nk; k += 128){
        float e = __expf(sp[k] - gmax);
        sp[k] = e;
        lsum += e;
    }
    float ws = warp_sum(lsum);
    if ((tid & 31) == 0) rsum[tid>>5] = ws;
    __syncthreads();
    float inv = 1.0f / (rsum[0]+rsum[1]+rsum[2]+rsum[3]);

    const int d    = tid & 63;
    const int half = tid >> 6;
    float acc = 0.f;
    for (int k = half; k < nk; k += 2){
        acc += sp[k] * qkv[(size_t)(b*TMAXS + k)*(3*DMODEL) + 2*DMODEL + h*HD + d];
    }
    if (half) yc[d] = acc;
    __syncthreads();
    if (!half)
        y[(size_t)(b*TMAXS + tq)*DMODEL + h*HD + d] = (acc + yc[d]) * inv;
}

// ---------------- host orchestration ----------------
#define SMEM_NN ((2*AS_BUF + 2*BS_NN_BUF)*4)
#define SMEM_NT ((2*AS_BUF + 2*BS_NT_BUF)*4)

extern "C" void kernel_launch(void* const* d_in, const int* in_sizes, int n_in,
                              void* d_out, int out_size)
{
    const int*   ids    = (const int*)  d_in[0];
    const float* wte    = (const float*)d_in[1];
    const float* wpe    = (const float*)d_in[2];
    const float* ln1_g  = (const float*)d_in[3];
    const float* ln1_b  = (const float*)d_in[4];
    const float* attn_w = (const float*)d_in[5];
    const float* attn_b = (const float*)d_in[6];
    const float* proj_w = (const float*)d_in[7];
    const float* proj_b = (const float*)d_in[8];
    const float* ln2_g  = (const float*)d_in[9];
    const float* ln2_b  = (const float*)d_in[10];
    const float* fc_w   = (const float*)d_in[11];
    const float* fc_b   = (const float*)d_in[12];
    const float* fc2_w  = (const float*)d_in[13];
    const float* fc2_b  = (const float*)d_in[14];
    const float* lnf_g  = (const float*)d_in[15];
    const float* lnf_b  = (const float*)d_in[16];
    float* out = (float*)d_out;

    float *x, *h, *qkv, *y, *fc;
    cudaGetSymbolAddress((void**)&x,   g_x);
    cudaGetSymbolAddress((void**)&h,   g_h);
    cudaGetSymbolAddress((void**)&qkv, g_qkv);
    cudaGetSymbolAddress((void**)&y,   g_y);
    cudaGetSymbolAddress((void**)&fc,  g_fc);

    cudaFuncSetAttribute(mma_gemm<1,false>, cudaFuncAttributeMaxDynamicSharedMemorySize, SMEM_NN);
    cudaFuncSetAttribute(mma_gemm<2,false>, cudaFuncAttributeMaxDynamicSharedMemorySize, SMEM_NN);
    cudaFuncSetAttribute(mma_gemm<3,false>, cudaFuncAttributeMaxDynamicSharedMemorySize, SMEM_NN);
    cudaFuncSetAttribute(mma_gemm<0,true >, cudaFuncAttributeMaxDynamicSharedMemorySize, SMEM_NT);

    embed_kernel<<<(MROWS*DMODEL + 255)/256, 256>>>(ids, wte, wpe, x);

    for (int l = 0; l < LAYERS; l++){
        layernorm_kernel<<<MROWS, 256>>>(x, h, ln1_g + l*DMODEL, ln1_b + l*DMODEL);

        mma_gemm<1,false><<<dim3(3*DMODEL/128, MROWS/128), 256, SMEM_NN>>>(
            h, attn_w + (size_t)l*DMODEL*3*DMODEL, attn_b + (size_t)l*3*DMODEL,
            nullptr, qkv, MROWS, 3*DMODEL, DMODEL);

        attention_kernel<<<dim3(TMAXS, NHEAD, BATCH), 128>>>(qkv, y);

        mma_gemm<2,false><<<dim3(DMODEL/128, MROWS/128), 256, SMEM_NN>>>(
            y, proj_w + (size_t)l*DMODEL*DMODEL, proj_b + (size_t)l*DMODEL,
            x, x, MROWS, DMODEL, DMODEL);

        layernorm_kernel<<<MROWS, 256>>>(x, h, ln2_g + l*DMODEL, ln2_b + l*DMODEL);

        mma_gemm<3,false><<<dim3(4*DMODEL/128, MROWS/128), 256, SMEM_NN>>>(
            h, fc_w + (size_t)l*DMODEL*4*DMODEL, fc_b + (size_t)l*4*DMODEL,
            nullptr, fc, MROWS, 4*DMODEL, DMODEL);

        mma_gemm<2,false><<<dim3(DMODEL/128, MROWS/128), 256, SMEM_NN>>>(
            fc, fc2_w + (size_t)l*4*DMODEL*DMODEL, fc2_b + (size_t)l*DMODEL,
            x, x, MROWS, DMODEL, 4*DMODEL);
    }

    layernorm_kernel<<<MROWS, 256>>>(x, h, lnf_g, lnf_b);

    mma_gemm<0,true><<<dim3((VOCAB + 127)/128, MROWS/128), 256, SMEM_NT>>>(
        h, wte, nullptr, nullptr, out, MROWS, VOCAB, DMODEL);
}